// round 14
// baseline (speedup 1.0000x reference)
#include <cuda_runtime.h>
#include <cuda_bf16.h>
#include <cstdint>

#define Bsz 32
#define Ssz 16
#define Dsz 4096
#define Hsz 32
#define HDsz 128
#define MAXLEN 2048

static __device__ float g_q[(size_t)Bsz * Hsz * Ssz * HDsz];          // 8 MB
static __device__ __nv_bfloat16 g_Xhi[3ull * 512 * 4096];
static __device__ __nv_bfloat16 g_Xlo[3ull * 512 * 4096];
static __device__ __nv_bfloat16 g_Whi[3ull * 4096 * 4096];            // 100 MB
static __device__ __nv_bfloat16 g_Wlo[3ull * 4096 * 4096];

extern __shared__ char _smraw[];

// ---------------- PTX helpers ----------------
__device__ __forceinline__ uint32_t elect_one_pred() {
    uint32_t pred;
    asm volatile("{\n\t.reg .pred p;\n\telect.sync _|p, 0xFFFFFFFF;\n\t"
                 "selp.b32 %0, 1, 0, p;\n\t}" : "=r"(pred));
    return pred;
}
__device__ __forceinline__ uint32_t smem_to_u32(const void* p) {
    uint32_t a;
    asm("{ .reg .u64 t; cvta.to.shared.u64 t, %1; cvt.u32.u64 %0, t; }" : "=r"(a) : "l"(p));
    return a;
}
#define MBARRIER_INIT(addr, cnt) \
    asm volatile("mbarrier.init.shared.b64 [%0], %1;" :: "r"((uint32_t)(addr)), "r"((uint32_t)(cnt)) : "memory")
#define MBARRIER_INVAL(addr) \
    asm volatile("mbarrier.inval.shared.b64 [%0];" :: "r"((uint32_t)(addr)) : "memory")
#define MBARRIER_WAIT_PARITY(mbar_smem_addr, phase_parity) do { \
    uint32_t _mbar = (uint32_t)(mbar_smem_addr); \
    uint32_t _parity = (uint32_t)(phase_parity); \
    uint32_t _done; \
    asm volatile("{\n\t.reg .pred p;\n\t" \
        "mbarrier.try_wait.parity.acquire.cta.shared::cta.b64 p, [%1], %2;\n\t" \
        "selp.b32 %0, 1, 0, p;\n\t}" : "=r"(_done) : "r"(_mbar), "r"(_parity) : "memory"); \
    if (!_done) { \
        asm volatile("{\n\t.reg .pred P1;\n\t" \
            "WAIT_LOOP_%=:\n\t" \
            "mbarrier.try_wait.parity.acquire.cta.shared::cta.b64 P1, [%0], %1, 0x989680;\n\t" \
            "@P1 bra.uni WAIT_DONE_%=;\n\t" \
            "bra.uni WAIT_LOOP_%=;\n\t" \
            "WAIT_DONE_%=:\n\t}" :: "r"(_mbar), "r"(_parity) : "memory"); \
    } \
} while(0)
#define TCGEN05_ALLOC(smem_addr, nCols) \
    asm volatile("tcgen05.alloc.cta_group::1.sync.aligned.shared::cta.b32 [%0], %1;" \
                 :: "r"((uint32_t)(smem_addr)), "r"((uint32_t)(nCols)) : "memory")
#define TCGEN05_DEALLOC(tmem, nCols) \
    asm volatile("tcgen05.dealloc.cta_group::1.sync.aligned.b32 %0, %1;" :: "r"(tmem), "r"((uint32_t)(nCols)))
#define TCGEN05_COMMIT(mbar) \
    asm volatile("tcgen05.commit.cta_group::1.mbarrier::arrive::one.shared::cluster.b64 [%0];" \
                 :: "r"((uint32_t)(mbar)) : "memory")
#define TCGEN05_FENCE_AFTER()  asm volatile("tcgen05.fence::after_thread_sync;" ::: "memory")
#define TCGEN05_WAIT_LD()      asm volatile("tcgen05.wait::ld.sync.aligned;" ::: "memory")
#define FENCE_PROXY_ASYNC()    asm volatile("fence.proxy.async.shared::cta;" ::: "memory")
#define CP_ASYNC16(dst, src) \
    asm volatile("cp.async.cg.shared.global [%0], [%1], 16;" :: "r"((uint32_t)(dst)), "l"(src) : "memory")
#define CP_COMMIT() asm volatile("cp.async.commit_group;" ::: "memory")
#define CP_WAIT0()  asm volatile("cp.async.wait_group 0;" ::: "memory")
#define CP_WAIT1()  asm volatile("cp.async.wait_group 1;" ::: "memory")
#define TCGEN05_LD_32X32B_X32(r, tmem_addr) \
    asm volatile("tcgen05.ld.sync.aligned.32x32b.x32.b32 " \
        "{%0, %1, %2, %3, %4, %5, %6, %7, %8, %9, %10, %11, %12, %13, %14, %15, " \
        " %16, %17, %18, %19, %20, %21, %22, %23, %24, %25, %26, %27, %28, %29, %30, %31}, [%32];" \
        : "=r"((r)[0]),  "=r"((r)[1]),  "=r"((r)[2]),  "=r"((r)[3]), \
          "=r"((r)[4]),  "=r"((r)[5]),  "=r"((r)[6]),  "=r"((r)[7]), \
          "=r"((r)[8]),  "=r"((r)[9]),  "=r"((r)[10]), "=r"((r)[11]), \
          "=r"((r)[12]), "=r"((r)[13]), "=r"((r)[14]), "=r"((r)[15]), \
          "=r"((r)[16]), "=r"((r)[17]), "=r"((r)[18]), "=r"((r)[19]), \
          "=r"((r)[20]), "=r"((r)[21]), "=r"((r)[22]), "=r"((r)[23]), \
          "=r"((r)[24]), "=r"((r)[25]), "=r"((r)[26]), "=r"((r)[27]), \
          "=r"((r)[28]), "=r"((r)[29]), "=r"((r)[30]), "=r"((r)[31]) \
        : "r"(tmem_addr))

#define SMEM_SWIZZLE_128B(off) ((off) ^ (((off) >> 3) & 0x70))
static constexpr uint64_t SMEM_DESC_BASE_SW128 =
    (uint64_t(2) << 61) | (uint64_t(1) << 46) | (uint64_t(64) << 32) | (uint64_t(1) << 16);
#define MAKE_SMEM_DESC(base_addr) (SMEM_DESC_BASE_SW128 | ((uint64_t)((base_addr) >> 4) & 0x3FFF))

#define MMA_IDESC 0x8200490u

#if defined(__CUDA_ARCH_FEAT_SM103_ALL) || defined(__CUDA_ARCH_FEAT_SM100_ALL) || !defined(__CUDA_ARCH__)
#define HAVE_TCGEN05 1
#else
#define HAVE_TCGEN05 0
#endif

#if HAVE_TCGEN05
__device__ __forceinline__ void mma_f16_ss(uint32_t d, uint64_t ad, uint64_t bd,
                                           uint32_t idesc, bool acc) {
    uint32_t en = acc ? 1u : 0u, z = 0u;
    asm volatile("{\n\t.reg .pred p;\n\tsetp.ne.u32 p, %5, 0;\n\t"
                 "tcgen05.mma.cta_group::1.kind::f16 [%0], %1, %2, %3, {%4, %4, %4, %4}, p;\n\t}"
                 :: "r"(d), "l"(ad), "l"(bd), "r"(idesc), "r"(z), "r"(en) : "memory");
}
#endif

__device__ __forceinline__ float2 ffma2(float2 a, float2 b, float2 c) {
    asm("fma.rn.f32x2 %0, %1, %2, %3;"
        : "=l"(reinterpret_cast<unsigned long long&>(c))
        : "l"(reinterpret_cast<unsigned long long&>(a)),
          "l"(reinterpret_cast<unsigned long long&>(b)),
          "l"(reinterpret_cast<unsigned long long&>(c)));
    return c;
}

// ---------------------------------------------------------------------------
// Tail copy kernel: all rows with pos >= Cv+Ssz of both caches. 0 smem ->
// co-resides with the 132KB-smem gemm blocks on the same SMs (parallel stream).
// ---------------------------------------------------------------------------
__global__ __launch_bounds__(256)
void copy_kernel(const float* __restrict__ Kold, const float* __restrict__ Vold,
                 const int* __restrict__ Cp,
                 float* __restrict__ Knew, float* __restrict__ Vnew)
{
    const int tid = threadIdx.x;
    const int Cv = Cp[0];
    const int rowInGrp = tid >> 5, wrd = tid & 31;
    const size_t stride = (size_t)gridDim.x * 8;
    for (size_t row = (size_t)blockIdx.x * 8 + rowInGrp; row < 4194304ull; row += stride) {
        const int cache = row >= 2097152ull;
        const size_t within = cache ? row - 2097152ull : row;
        const int pos = (int)(within & (MAXLEN - 1));
        if (pos < Cv + Ssz) continue;
        const float4* src = (const float4*)(cache ? Vold : Kold) + within * 32 + wrd;
        float4* dst = (float4*)(cache ? Vnew : Knew) + within * 32 + wrd;
        *dst = *src;
    }
}

// ---------------------------------------------------------------------------
// Prep: X split [0,3072), W transpose+split [3072,15360).
// ---------------------------------------------------------------------------
__global__ __launch_bounds__(256)
void prep_kernel(const float* __restrict__ Q, const float* __restrict__ K,
                 const float* __restrict__ V,
                 const float* __restrict__ w0, const float* __restrict__ w1,
                 const float* __restrict__ w2)
{
    __shared__ float ts[64][65];
    const int bx = blockIdx.x, tid = threadIdx.x;

    if (bx < 3072) {
        const int proj = bx >> 10;
        const float* src = (proj == 0) ? Q : ((proj == 1) ? K : V);
        const size_t off = ((size_t)(bx & 1023) * 256 + tid) * 8;
        float4 a = *(const float4*)(src + off);
        float4 b = *(const float4*)(src + off + 4);
        float v[8] = {a.x, a.y, a.z, a.w, b.x, b.y, b.z, b.w};
        __align__(16) __nv_bfloat16 hi[8], lo[8];
#pragma unroll
        for (int j = 0; j < 8; j++) {
            hi[j] = __float2bfloat16(v[j]);
            lo[j] = __float2bfloat16(v[j] - __bfloat162float(hi[j]));
        }
        const size_t dst = (size_t)proj * (512ull * 4096) + off;
        *(uint4*)(g_Xhi + dst) = *(const uint4*)hi;
        *(uint4*)(g_Xlo + dst) = *(const uint4*)lo;
        return;
    }

    const int wb = bx - 3072;
    const int proj = wb >> 12;
    const int t = wb & 4095;
    const int k0 = (t >> 6) * 64, n0 = (t & 63) * 64;
    const float* W = (proj == 0) ? w0 : ((proj == 1) ? w1 : w2);

    {
        const int r = tid >> 2, c16 = (tid & 3) * 16;
#pragma unroll
        for (int j = 0; j < 4; j++) {
            float4 f = *(const float4*)&W[(size_t)(k0 + r) * 4096 + n0 + c16 + j * 4];
            ts[r][c16 + j * 4 + 0] = f.x;  ts[r][c16 + j * 4 + 1] = f.y;
            ts[r][c16 + j * 4 + 2] = f.z;  ts[r][c16 + j * 4 + 3] = f.w;
        }
    }
    __syncthreads();
    {
        const int nr = tid >> 2, kc = (tid & 3) * 16;
        __align__(16) __nv_bfloat16 hi[16], lo[16];
#pragma unroll
        for (int j = 0; j < 16; j++) {
            float x = ts[kc + j][nr];
            hi[j] = __float2bfloat16(x);
            lo[j] = __float2bfloat16(x - __bfloat162float(hi[j]));
        }
        const size_t base = (size_t)proj * (4096ull * 4096) + (size_t)(n0 + nr) * 4096 + k0 + kc;
        ((uint4*)(g_Whi + base))[0] = ((const uint4*)hi)[0];
        ((uint4*)(g_Whi + base))[1] = ((const uint4*)hi)[1];
        ((uint4*)(g_Wlo + base))[0] = ((const uint4*)lo)[0];
        ((uint4*)(g_Wlo + base))[1] = ((const uint4*)lo)[1];
    }
}

// ---------------------------------------------------------------------------
// tcgen05 GEMM + cp.async pipeline (R12-proven). One 128x128 tile per block.
// ---------------------------------------------------------------------------
__global__ __launch_bounds__(256)
void gemm_kernel(const float* __restrict__ Qin, const float* __restrict__ Kin,
                 const float* __restrict__ Vin,
                 const float* __restrict__ w0, const float* __restrict__ w1,
                 const float* __restrict__ w2,
                 const float* __restrict__ emb, const int* __restrict__ Cp,
                 float* __restrict__ outKc, float* __restrict__ outVc)
{
    const int tid = threadIdx.x;
    const int h = blockIdx.x, m0 = blockIdx.y * 128, which = blockIdx.z;
    const int Cv = Cp[0];

#if HAVE_TCGEN05
    char* sm = _smraw;
    const uint32_t smb = smem_to_u32(sm);
    const int wid = tid >> 5, lane = tid & 31;
    const int n0 = h * 128;

    if (wid == 0) TCGEN05_ALLOC(smb + 0, 512);
    if (tid == 0) { MBARRIER_INIT(smb + 8, 1); MBARRIER_INIT(smb + 16, 1); }
    __syncthreads();
    uint32_t tmem;
    asm volatile("ld.shared.b32 %0, [%1];" : "=r"(tmem) : "r"(smb + 0));

    const int r = tid >> 1;
    const int u0 = (tid & 1) * 4;
    const uint4* pAh = (const uint4*)(g_Xhi + (size_t)which * (512ull * 4096) + (size_t)(m0 + r) * 4096);
    const uint4* pAl = (const uint4*)(g_Xlo + (size_t)which * (512ull * 4096) + (size_t)(m0 + r) * 4096);
    const uint4* pBh = (const uint4*)(g_Whi + (size_t)which * (4096ull * 4096) + (size_t)(n0 + r) * 4096);
    const uint4* pBl = (const uint4*)(g_Wlo + (size_t)which * (4096ull * 4096) + (size_t)(n0 + r) * 4096);

    uint32_t soff[4];
#pragma unroll
    for (int j = 0; j < 4; j++)
        soff[j] = SMEM_SWIZZLE_128B(r * 128 + (u0 + j) * 16);

#define ISSUE_CP(c, stBase) do { \
        const int kb_ = (c) * 8 + u0; \
        _Pragma("unroll") \
        for (int j = 0; j < 4; j++) CP_ASYNC16((stBase) +         soff[j], pAh + kb_ + j); \
        _Pragma("unroll") \
        for (int j = 0; j < 4; j++) CP_ASYNC16((stBase) + 16384 + soff[j], pAl + kb_ + j); \
        _Pragma("unroll") \
        for (int j = 0; j < 4; j++) CP_ASYNC16((stBase) + 32768 + soff[j], pBh + kb_ + j); \
        _Pragma("unroll") \
        for (int j = 0; j < 4; j++) CP_ASYNC16((stBase) + 49152 + soff[j], pBl + kb_ + j); \
        CP_COMMIT(); \
    } while (0)

    ISSUE_CP(0, smb + 1024u);
    int ph0 = 0, ph1 = 0;
    for (int c = 0; c < 64; c++) {
        const int st = c & 1;
        const uint32_t so = smb + 1024u + (uint32_t)st * 65536u;
        if (c < 63) {
            const int nst = (c + 1) & 1;
            if (c >= 1) {
                if (nst == 0) { MBARRIER_WAIT_PARITY(smb + 8, ph0); ph0 ^= 1; }
                else          { MBARRIER_WAIT_PARITY(smb + 16, ph1); ph1 ^= 1; }
            }
            ISSUE_CP(c + 1, smb + 1024u + (uint32_t)nst * 65536u);
            CP_WAIT1();
        } else {
            CP_WAIT0();
        }
        __syncthreads();
        FENCE_PROXY_ASYNC();
        if (tid < 32 && elect_one_pred()) {
            const uint64_t dAh = MAKE_SMEM_DESC(so);
            const uint64_t dAl = MAKE_SMEM_DESC(so + 16384);
            const uint64_t dBh = MAKE_SMEM_DESC(so + 32768);
            const uint64_t dBl = MAKE_SMEM_DESC(so + 49152);
#pragma unroll
            for (int j = 0; j < 4; j++)
                mma_f16_ss(tmem, dAh + j * 2, dBh + j * 2, MMA_IDESC, !(c == 0 && j == 0));
#pragma unroll
            for (int j = 0; j < 4; j++)
                mma_f16_ss(tmem, dAl + j * 2, dBh + j * 2, MMA_IDESC, true);
#pragma unroll
            for (int j = 0; j < 4; j++)
                mma_f16_ss(tmem, dAh + j * 2, dBl + j * 2, MMA_IDESC, true);
            TCGEN05_COMMIT(smb + 8 + st * 8);
        }
    }
    MBARRIER_WAIT_PARITY(smb + 16, ph1);
    TCGEN05_FENCE_AFTER();

    if (wid < 4) {
        const int m = m0 + wid * 32 + lane;
        const int b = m >> 4, s = m & 15;
        const float* cosp = emb + s * HDsz;
        const float* sinp = emb + Ssz * HDsz + s * HDsz;
        float* dst = (which == 0)
            ? g_q + ((size_t)(b * Hsz + h) * Ssz + s) * HDsz
            : ((which == 1)
               ? outKc + ((size_t)(b * Hsz + h) * MAXLEN + (size_t)(Cv + s)) * HDsz
               : outVc + ((size_t)(b * Hsz + h) * MAXLEN + (size_t)(Cv + s)) * HDsz);
#pragma unroll
        for (int p = 0; p < 2; p++) {
            uint32_t x1[32], x2[32];
            TCGEN05_LD_32X32B_X32(x1, tmem + p * 32);
            TCGEN05_LD_32X32B_X32(x2, tmem + 64 + p * 32);
            TCGEN05_WAIT_LD();
            if (which == 2) {
#pragma unroll
                for (int j = 0; j < 32; j++) {
                    dst[p * 32 + j]      = __uint_as_float(x1[j]);
                    dst[64 + p * 32 + j] = __uint_as_float(x2[j]);
                }
            } else {
#pragma unroll
                for (int j = 0; j < 32; j++) {
                    const int d = p * 32 + j;
                    const float a = __uint_as_float(x1[j]);
                    const float bb = __uint_as_float(x2[j]);
                    dst[d]      = a * cosp[d] - bb * sinp[d];
                    dst[d + 64] = bb * cosp[d + 64] + a * sinp[d + 64];
                }
            }
        }
    }
    __syncthreads();
    if (tid == 0) { MBARRIER_INVAL(smb + 8); MBARRIER_INVAL(smb + 16); }
    __syncthreads();
    if (wid == 0) TCGEN05_DEALLOC(tmem, 512);

#else   // ---------------- generic-target fallback: FFMA2 GEMM ----------------
    const float* X = (which == 0) ? Qin : ((which == 1) ? Kin : Vin);
    const float* W = (which == 0) ? w0 : ((which == 1) ? w1 : w2);

    __shared__ float As[2][16][132];
    __shared__ float Bs[2][16][128];

    const int tx = tid & 15;
    const int ty = tid >> 4;
    const int n0f = h * 128;

    float2 acc2[8][4];
#pragma unroll
    for (int i = 0; i < 8; i++)
#pragma unroll
        for (int j = 0; j < 4; j++) acc2[i][j] = make_float2(0.f, 0.f);

    const int r_x = tid >> 2, c_x = tid & 3;
    const int r_w = tid >> 5, c_w = tid & 31;
    float4 xa0, xa1, wb0, wb1;

    xa0 = *(const float4*)&X[(size_t)(m0 + r_x) * Dsz + c_x * 4];
    xa1 = *(const float4*)&X[(size_t)(m0 + r_x + 64) * Dsz + c_x * 4];
    wb0 = *(const float4*)&W[(size_t)(r_w) * Dsz + n0f + c_w * 4];
    wb1 = *(const float4*)&W[(size_t)(r_w + 8) * Dsz + n0f + c_w * 4];

    As[0][c_x * 4 + 0][r_x] = xa0.x;  As[0][c_x * 4 + 1][r_x] = xa0.y;
    As[0][c_x * 4 + 2][r_x] = xa0.z;  As[0][c_x * 4 + 3][r_x] = xa0.w;
    As[0][c_x * 4 + 0][r_x + 64] = xa1.x;  As[0][c_x * 4 + 1][r_x + 64] = xa1.y;
    As[0][c_x * 4 + 2][r_x + 64] = xa1.z;  As[0][c_x * 4 + 3][r_x + 64] = xa1.w;
    *(float4*)&Bs[0][r_w][c_w * 4]     = wb0;
    *(float4*)&Bs[0][r_w + 8][c_w * 4] = wb1;
    __syncthreads();

    int cur = 0;
    for (int kt = 0; kt < 256; kt++) {
        if (kt < 255) {
            const int k0n = (kt + 1) * 16;
            xa0 = *(const float4*)&X[(size_t)(m0 + r_x) * Dsz + k0n + c_x * 4];
            xa1 = *(const float4*)&X[(size_t)(m0 + r_x + 64) * Dsz + k0n + c_x * 4];
            wb0 = *(const float4*)&W[(size_t)(k0n + r_w) * Dsz + n0f + c_w * 4];
            wb1 = *(const float4*)&W[(size_t)(k0n + r_w + 8) * Dsz + n0f + c_w * 4];
        }
#pragma unroll
        for (int k = 0; k < 16; k++) {
            float4 a0 = *(const float4*)&As[cur][k][ty * 8];
            float4 a1 = *(const float4*)&As[cur][k][ty * 8 + 4];
            float4 b0 = *(const float4*)&Bs[cur][k][tx * 4];
            float4 b1 = *(const float4*)&Bs[cur][k][64 + tx * 4];
            const float av[8] = {a0.x, a0.y, a0.z, a0.w, a1.x, a1.y, a1.z, a1.w};
            const float2 bp[4] = {make_float2(b0.x, b0.y), make_float2(b0.z, b0.w),
                                  make_float2(b1.x, b1.y), make_float2(b1.z, b1.w)};
#pragma unroll
            for (int i = 0; i < 8; i++) {
                const float2 ad = make_float2(av[i], av[i]);
#pragma unroll
                for (int jp = 0; jp < 4; jp++)
                    acc2[i][jp] = ffma2(ad, bp[jp], acc2[i][jp]);
            }
        }
        if (kt < 255) {
            const int nb = cur ^ 1;
            As[nb][c_x * 4 + 0][r_x] = xa0.x;  As[nb][c_x * 4 + 1][r_x] = xa0.y;
            As[nb][c_x * 4 + 2][r_x] = xa0.z;  As[nb][c_x * 4 + 3][r_x] = xa0.w;
            As[nb][c_x * 4 + 0][r_x + 64] = xa1.x;  As[nb][c_x * 4 + 1][r_x + 64] = xa1.y;
            As[nb][c_x * 4 + 2][r_x + 64] = xa1.z;  As[nb][c_x * 4 + 3][r_x + 64] = xa1.w;
            *(float4*)&Bs[nb][r_w][c_w * 4]     = wb0;
            *(float4*)&Bs[nb][r_w + 8][c_w * 4] = wb1;
        }
        __syncthreads();
        cur ^= 1;
    }

#pragma unroll
    for (int i = 0; i < 8; i++) {
        const int m = m0 + ty * 8 + i;
        const int b = m >> 4;
        const int s = m & 15;
        const float* accr = (const float*)&acc2[i][0];
        if (which == 2) {
            float* vb = outVc + ((size_t)(b * Hsz + h) * MAXLEN + (size_t)(Cv + s)) * HDsz;
#pragma unroll
            for (int j = 0; j < 4; j++) {
                vb[tx * 4 + j]      = accr[j];
                vb[64 + tx * 4 + j] = accr[j + 4];
            }
        } else {
            const float* cosp = emb + s * HDsz;
            const float* sinp = emb + Ssz * HDsz + s * HDsz;
            float* dst = (which == 0)
                ? (g_q + ((size_t)(b * Hsz + h) * Ssz + s) * HDsz)
                : (outKc + ((size_t)(b * Hsz + h) * MAXLEN + (size_t)(Cv + s)) * HDsz);
#pragma unroll
            for (int j = 0; j < 4; j++) {
                const int d1 = tx * 4 + j;
                const float x1 = accr[j];
                const float x2 = accr[j + 4];
                dst[d1]      = x1 * cosp[d1]      - x2 * sinp[d1];
                dst[d1 + 64] = x2 * cosp[d1 + 64] + x1 * sinp[d1 + 64];
            }
        }
    }
#endif
}

// ---------------------------------------------------------------------------
// Attention (R12-proven core): one (b,h) per block, 256 threads; write-through
// of rows < C. No copy blocks (tail copy runs on the parallel stream).
// ---------------------------------------------------------------------------
__global__ __launch_bounds__(256)
void attn_kernel(const float* __restrict__ KcOld, const float* __restrict__ VcOld,
                 const int* __restrict__ Cp, float* __restrict__ out,
                 float* __restrict__ outKc, float* __restrict__ outVc)
{
    const int tid = threadIdx.x;
    const int Cv = Cp[0];

    float* sm = (float*)_smraw;
    float* qs = sm;                  // 16*128
    float* Ks = sm + 2048;           // 64*132
    float* Vs = Ks + 64 * 132;       // 64*132

    const int w = tid >> 5;
    const int l = tid & 31;
    const int bh = blockIdx.x;
    const int Lv = Cv + Ssz;

    const float* KbO = KcOld + (size_t)bh * MAXLEN * HDsz;
    const float* VbO = VcOld + (size_t)bh * MAXLEN * HDsz;
    float* KbN = outKc + (size_t)bh * MAXLEN * HDsz;
    float* VbN = outVc + (size_t)bh * MAXLEN * HDsz;
    const float* qg = g_q + (size_t)bh * Ssz * HDsz;

    for (int f = tid; f < Ssz * HDsz / 4; f += 256)
        ((float4*)qs)[f] = ((const float4*)qg)[f];

    const int q0 = 2 * w, q1 = 2 * w + 1;
    float m0r = -1e30f, m1r = -1e30f, l0r = 0.f, l1r = 0.f;
    float2 o0[2] = {make_float2(0.f, 0.f), make_float2(0.f, 0.f)};
    float2 o1[2] = {make_float2(0.f, 0.f), make_float2(0.f, 0.f)};
    const float SCALE = 0.08838834764831845f;
    const int ntiles = (Lv + 63) >> 6;

    for (int t = 0; t < ntiles; t++) {
        const int tile0 = t << 6;
        __syncthreads();
        for (int f = tid; f < 64 * 32; f += 256) {
            const int key = f >> 5;
            const int d4 = (f & 31) * 4;
            const int pos = tile0 + key;
            const size_t gi = (size_t)pos * HDsz + d4;
            float4 kv, vv;
            if (pos < Cv) {
                kv = *(const float4*)&KbO[gi];
                vv = *(const float4*)&VbO[gi];
                *(float4*)&KbN[gi] = kv;     // write-through copy
                *(float4*)&VbN[gi] = vv;
            } else {
                kv = *(const float4*)&KbN[gi];
                vv = *(const float4*)&VbN[gi];
            }
            *(float4*)&Ks[key * 132 + d4] = kv;
            *(float4*)&Vs[key * 132 + d4] = vv;
        }
        __syncthreads();

        const float4* kr0 = (const float4*)(Ks + l * 132);
        const float4* kr1 = (const float4*)(Ks + (l + 32) * 132);
        const float4* qr0 = (const float4*)(qs + q0 * HDsz);
        const float4* qr1 = (const float4*)(qs + q1 * HDsz);
        float2 s00 = make_float2(0.f, 0.f), s01 = s00, s10 = s00, s11 = s00;
#pragma unroll 8
        for (int d4 = 0; d4 < 32; d4++) {
            const float4 qa = qr0[d4], qb = qr1[d4];
            const float4 ka = kr0[d4], kb = kr1[d4];
            const float2 qa0 = make_float2(qa.x, qa.y), qa1 = make_float2(qa.z, qa.w);
            const float2 qb0 = make_float2(qb.x, qb.y), qb1 = make_float2(qb.z, qb.w);
            const float2 ka0 = make_float2(ka.x, ka.y), ka1 = make_float2(ka.z, ka.w);
            const float2 kb0 = make_float2(kb.x, kb.y), kb1 = make_float2(kb.z, kb.w);
            s00 = ffma2(qa0, ka0, s00);  s00 = ffma2(qa1, ka1, s00);
            s01 = ffma2(qa0, kb0, s01);  s01 = ffma2(qa1, kb1, s01);
            s10 = ffma2(qb0, ka0, s10);  s10 = ffma2(qb1, ka1, s10);
            s11 = ffma2(qb0, kb0, s11);  s11 = ffma2(qb1, kb1, s11);
        }
        const int kp0 = tile0 + l, kp1 = tile0 + l + 32;
        const int qp0 = Cv + q0,  qp1 = Cv + q1;
        float x00 = (kp0 < Lv && kp0 <= qp0) ? (s00.x + s00.y) * SCALE : -1e30f;
        float x01 = (kp1 < Lv && kp1 <= qp0) ? (s01.x + s01.y) * SCALE : -1e30f;
        float x10 = (kp0 < Lv && kp0 <= qp1) ? (s10.x + s10.y) * SCALE : -1e30f;
        float x11 = (kp1 < Lv && kp1 <= qp1) ? (s11.x + s11.y) * SCALE : -1e30f;

        float mt0 = fmaxf(x00, x01);
        float mt1 = fmaxf(x10, x11);
#pragma unroll
        for (int off = 16; off; off >>= 1) {
            mt0 = fmaxf(mt0, __shfl_xor_sync(0xffffffffu, mt0, off));
            mt1 = fmaxf(mt1, __shfl_xor_sync(0xffffffffu, mt1, off));
        }
        const float nm0 = fmaxf(m0r, mt0), nm1 = fmaxf(m1r, mt1);
        const float f0 = __expf(m0r - nm0), f1 = __expf(m1r - nm1);
        const float p00 = __expf(x00 - nm0), p01 = __expf(x01 - nm0);
        const float p10 = __expf(x10 - nm1), p11 = __expf(x11 - nm1);
        float sum0 = p00 + p01, sum1 = p10 + p11;
#pragma unroll
        for (int off = 16; off; off >>= 1) {
            sum0 += __shfl_xor_sync(0xffffffffu, sum0, off);
            sum1 += __shfl_xor_sync(0xffffffffu, sum1, off);
        }
        l0r = l0r * f0 + sum0;  l1r = l1r * f1 + sum1;
        m0r = nm0;  m1r = nm1;
        o0[0].x *= f0; o0[0].y *= f0; o0[1].x *= f0; o0[1].y *= f0;
        o1[0].x *= f1; o1[0].y *= f1; o1[1].x *= f1; o1[1].y *= f1;

#pragma unroll 8
        for (int k = 0; k < 32; k++) {
            const float pv0 = __shfl_sync(0xffffffffu, p00, k);
            const float pv1 = __shfl_sync(0xffffffffu, p10, k);
            const float4 v4 = *(const float4*)&Vs[k * 132 + l * 4];
            const float2 vp0 = make_float2(v4.x, v4.y), vp1 = make_float2(v4.z, v4.w);
            const float2 pv02 = make_float2(pv0, pv0), pv12 = make_float2(pv1, pv1);
            o0[0] = ffma2(pv02, vp0, o0[0]);  o0[1] = ffma2(pv02, vp1, o0[1]);
            o1[0] = ffma2(pv12, vp0, o1[0]);  o1[1] = ffma2(pv12, vp1, o1[1]);
        }
#pragma unroll 8
        for (int k = 0; k < 32; k++) {
            const float pv0 = __shfl_sync(0xffffffffu, p01, k);
            const float pv1 = __shfl_sync(0xffffffffu, p11, k);
            const float4 v4 = *(const float4*)&Vs[(k + 32) * 132 + l * 4];
            const float2 vp0 = make_float2(v4.x, v4.y), vp1 = make_float2(v4.z, v4.w);
            const float2 pv02 = make_float2(pv0, pv0), pv12 = make_float2(pv1, pv1);
            o0[0] = ffma2(pv02, vp0, o0[0]);  o0[1] = ffma2(pv02, vp1, o0[1]);
            o1[0] = ffma2(pv12, vp0, o1[0]);  o1[1] = ffma2(pv12, vp1, o1[1]);
        }
    }

    const int b = bh >> 5;
    const int h = bh & 31;
    const float inv0 = 1.f / l0r, inv1 = 1.f / l1r;
    float4 r0 = make_float4(o0[0].x * inv0, o0[0].y * inv0, o0[1].x * inv0, o0[1].y * inv0);
    float4 r1 = make_float4(o1[0].x * inv1, o1[0].y * inv1, o1[1].x * inv1, o1[1].y * inv1);
    *(float4*)&out[((size_t)(b * Ssz + q0) * Dsz) + h * HDsz + l * 4] = r0;
    *(float4*)&out[((size_t)(b * Ssz + q1) * Dsz) + h * HDsz + l * 4] = r1;
}

// ---------------------------------------------------------------------------
// Launch:
//   stream0: prep -> gemm -> attn
//   sB:      [after prep] tail copy kernel (0 smem; co-resides with gemm/attn)
//   join:    stream0 waits sB at the end.
// ---------------------------------------------------------------------------
extern "C" void kernel_launch(void* const* d_in, const int* in_sizes, int n_in,
                              void* d_out, int out_size)
{
    const float* Q      = (const float*)d_in[0];
    const float* K      = (const float*)d_in[1];
    const float* V      = (const float*)d_in[2];
    const float* Kcache = (const float*)d_in[3];
    const float* Vcache = (const float*)d_in[4];
    const float* w0     = (const float*)d_in[5];
    const float* w1     = (const float*)d_in[6];
    const float* w2     = (const float*)d_in[7];
    const float* emb    = (const float*)d_in[8];
    const int*   Cp     = (const int*)d_in[9];
    float* out = (float*)d_out;

    const size_t outsz   = (size_t)Bsz * Ssz * Dsz;
    const size_t cachesz = (size_t)Bsz * Hsz * MAXLEN * HDsz;
    float* outKc = out + outsz;
    float* outVc = outKc + cachesz;

    static cudaStream_t sB = nullptr;
    static cudaEvent_t eFork = nullptr, eJoin = nullptr;
    if (!sB) {
        cudaStreamCreateWithFlags(&sB, cudaStreamNonBlocking);
        cudaEventCreateWithFlags(&eFork, cudaEventDisableTiming);
        cudaEventCreateWithFlags(&eJoin, cudaEventDisableTiming);
    }

    // 1) prep: X/W split (stream 0)
    prep_kernel<<<15360, 256>>>(Q, K, V, w0, w1, w2);

    // fork: tail copy on sB, concurrent with gemm + attn
    cudaEventRecord(eFork, 0);
    cudaStreamWaitEvent(sB, eFork, 0);
    copy_kernel<<<296, 256, 0, sB>>>(Kcache, Vcache, Cp, outKc, outVc);

    // 2) projections (stream 0)
    const int gsmem = 1024 + 2 * 65536;   // 132,096 B
    cudaFuncSetAttribute(gemm_kernel, cudaFuncAttributeMaxDynamicSharedMemorySize, gsmem);
    gemm_kernel<<<dim3(32, 4, 3), 256, gsmem>>>(Q, K, V, w0, w1, w2, emb, Cp, outKc, outVc);

    // 3) attention + write-through (stream 0)
    const int asmem = (16 * 128 + 2 * 64 * 132) * 4;   // 75,776 B
    cudaFuncSetAttribute(attn_kernel, cudaFuncAttributeMaxDynamicSharedMemorySize, asmem);
    attn_kernel<<<1024, 256, asmem>>>(Kcache, Vcache, Cp, out, outKc, outVc);

    // join sB into stream 0
    cudaEventRecord(eJoin, sB);
    cudaStreamWaitEvent(0, eJoin, 0);
}

// round 17
// speedup vs baseline: 1.1629x; 1.1629x over previous
#include <cuda_runtime.h>
#include <cuda_fp16.h>
#include <cstdint>

#define Bsz 32
#define Ssz 16
#define Dsz 4096
#define Hsz 32
#define HDsz 128
#define MAXLEN 2048

static __device__ float g_q[(size_t)Bsz * Hsz * Ssz * HDsz];          // 8 MB
static __device__ __half g_Xhi[3ull * 512 * 4096];                    // fp16 hi of X
static __device__ __half g_Xlo[3ull * 512 * 4096];                    // fp16 lo of X
static __device__ __half g_W[3ull * 4096 * 4096];                     // fp16 W (single), 100 MB

extern __shared__ char _smraw[];

// ---------------- PTX helpers ----------------
__device__ __forceinline__ uint32_t elect_one_pred() {
    uint32_t pred;
    asm volatile("{\n\t.reg .pred p;\n\telect.sync _|p, 0xFFFFFFFF;\n\t"
                 "selp.b32 %0, 1, 0, p;\n\t}" : "=r"(pred));
    return pred;
}
__device__ __forceinline__ uint32_t smem_to_u32(const void* p) {
    uint32_t a;
    asm("{ .reg .u64 t; cvta.to.shared.u64 t, %1; cvt.u32.u64 %0, t; }" : "=r"(a) : "l"(p));
    return a;
}
#define MBARRIER_INIT(addr, cnt) \
    asm volatile("mbarrier.init.shared.b64 [%0], %1;" :: "r"((uint32_t)(addr)), "r"((uint32_t)(cnt)) : "memory")
#define MBARRIER_INVAL(addr) \
    asm volatile("mbarrier.inval.shared.b64 [%0];" :: "r"((uint32_t)(addr)) : "memory")
#define MBARRIER_WAIT_PARITY(mbar_smem_addr, phase_parity) do { \
    uint32_t _mbar = (uint32_t)(mbar_smem_addr); \
    uint32_t _parity = (uint32_t)(phase_parity); \
    uint32_t _done; \
    asm volatile("{\n\t.reg .pred p;\n\t" \
        "mbarrier.try_wait.parity.acquire.cta.shared::cta.b64 p, [%1], %2;\n\t" \
        "selp.b32 %0, 1, 0, p;\n\t}" : "=r"(_done) : "r"(_mbar), "r"(_parity) : "memory"); \
    if (!_done) { \
        asm volatile("{\n\t.reg .pred P1;\n\t" \
            "WAIT_LOOP_%=:\n\t" \
            "mbarrier.try_wait.parity.acquire.cta.shared::cta.b64 P1, [%0], %1, 0x989680;\n\t" \
            "@P1 bra.uni WAIT_DONE_%=;\n\t" \
            "bra.uni WAIT_LOOP_%=;\n\t" \
            "WAIT_DONE_%=:\n\t}" :: "r"(_mbar), "r"(_parity) : "memory"); \
    } \
} while(0)
#define TCGEN05_ALLOC(smem_addr, nCols) \
    asm volatile("tcgen05.alloc.cta_group::1.sync.aligned.shared::cta.b32 [%0], %1;" \
                 :: "r"((uint32_t)(smem_addr)), "r"((uint32_t)(nCols)) : "memory")
#define TCGEN05_DEALLOC(tmem, nCols) \
    asm volatile("tcgen05.dealloc.cta_group::1.sync.aligned.b32 %0, %1;" :: "r"(tmem), "r"((uint32_t)(nCols)))
#define TCGEN05_COMMIT(mbar) \
    asm volatile("tcgen05.commit.cta_group::1.mbarrier::arrive::one.shared::cluster.b64 [%0];" \
                 :: "r"((uint32_t)(mbar)) : "memory")
#define TCGEN05_FENCE_AFTER()  asm volatile("tcgen05.fence::after_thread_sync;" ::: "memory")
#define TCGEN05_WAIT_LD()      asm volatile("tcgen05.wait::ld.sync.aligned;" ::: "memory")
#define FENCE_PROXY_ASYNC()    asm volatile("fence.proxy.async.shared::cta;" ::: "memory")
#define CP_ASYNC16(dst, src) \
    asm volatile("cp.async.cg.shared.global [%0], [%1], 16;" :: "r"((uint32_t)(dst)), "l"(src) : "memory")
#define CP_COMMIT() asm volatile("cp.async.commit_group;" ::: "memory")
#define CP_WAIT0()  asm volatile("cp.async.wait_group 0;" ::: "memory")
#define CP_WAIT1()  asm volatile("cp.async.wait_group 1;" ::: "memory")
#define TCGEN05_LD_32X32B_X32(r, tmem_addr) \
    asm volatile("tcgen05.ld.sync.aligned.32x32b.x32.b32 " \
        "{%0, %1, %2, %3, %4, %5, %6, %7, %8, %9, %10, %11, %12, %13, %14, %15, " \
        " %16, %17, %18, %19, %20, %21, %22, %23, %24, %25, %26, %27, %28, %29, %30, %31}, [%32];" \
        : "=r"((r)[0]),  "=r"((r)[1]),  "=r"((r)[2]),  "=r"((r)[3]), \
          "=r"((r)[4]),  "=r"((r)[5]),  "=r"((r)[6]),  "=r"((r)[7]), \
          "=r"((r)[8]),  "=r"((r)[9]),  "=r"((r)[10]), "=r"((r)[11]), \
          "=r"((r)[12]), "=r"((r)[13]), "=r"((r)[14]), "=r"((r)[15]), \
          "=r"((r)[16]), "=r"((r)[17]), "=r"((r)[18]), "=r"((r)[19]), \
          "=r"((r)[20]), "=r"((r)[21]), "=r"((r)[22]), "=r"((r)[23]), \
          "=r"((r)[24]), "=r"((r)[25]), "=r"((r)[26]), "=r"((r)[27]), \
          "=r"((r)[28]), "=r"((r)[29]), "=r"((r)[30]), "=r"((r)[31]) \
        : "r"(tmem_addr))

#define SMEM_SWIZZLE_128B(off) ((off) ^ (((off) >> 3) & 0x70))
static constexpr uint64_t SMEM_DESC_BASE_SW128 =
    (uint64_t(2) << 61) | (uint64_t(1) << 46) | (uint64_t(64) << 32) | (uint64_t(1) << 16);
#define MAKE_SMEM_DESC(base_addr) (SMEM_DESC_BASE_SW128 | ((uint64_t)((base_addr) >> 4) & 0x3FFF))

// idesc fp16: F32 acc(1<<4) | FP16 A(0<<7) | FP16 B(0<<10) | N=128(16<<17) | M=128(8<<24)
#define MMA_IDESC_F16 0x8200010u

#if defined(__CUDA_ARCH_FEAT_SM103_ALL) || defined(__CUDA_ARCH_FEAT_SM100_ALL) || !defined(__CUDA_ARCH__)
#define HAVE_TCGEN05 1
#else
#define HAVE_TCGEN05 0
#endif

#if HAVE_TCGEN05
__device__ __forceinline__ void mma_f16_ss(uint32_t d, uint64_t ad, uint64_t bd,
                                           uint32_t idesc, bool acc) {
    uint32_t en = acc ? 1u : 0u, z = 0u;
    asm volatile("{\n\t.reg .pred p;\n\tsetp.ne.u32 p, %5, 0;\n\t"
                 "tcgen05.mma.cta_group::1.kind::f16 [%0], %1, %2, %3, {%4, %4, %4, %4}, p;\n\t}"
                 :: "r"(d), "l"(ad), "l"(bd), "r"(idesc), "r"(z), "r"(en) : "memory");
}
#endif

__device__ __forceinline__ float2 ffma2(float2 a, float2 b, float2 c) {
    asm("fma.rn.f32x2 %0, %1, %2, %3;"
        : "=l"(reinterpret_cast<unsigned long long&>(c))
        : "l"(reinterpret_cast<unsigned long long&>(a)),
          "l"(reinterpret_cast<unsigned long long&>(b)),
          "l"(reinterpret_cast<unsigned long long&>(c)));
    return c;
}

// copy rows with pos >= Cv+Ssz across both caches (tail)
__device__ __forceinline__ void tail_copy(size_t rowStart, size_t rowEnd, int nBlocks,
                                          int cb, int tid, int Cv,
                                          const float* Kold, const float* Vold,
                                          float* Knew, float* Vnew)
{
    const int rowInGrp = tid >> 5, wrd = tid & 31;
    const size_t stride = (size_t)nBlocks * 8;
    for (size_t row = rowStart + (size_t)cb * 8 + rowInGrp; row < rowEnd; row += stride) {
        const int cache = row >= 2097152ull;
        const size_t within = cache ? row - 2097152ull : row;
        const int pos = (int)(within & (MAXLEN - 1));
        if (pos < Cv + Ssz) continue;
        const float4* src = (const float4*)(cache ? Vold : Kold) + within * 32 + wrd;
        float4* dst = (float4*)(cache ? Vnew : Knew) + within * 32 + wrd;
        *dst = *src;
    }
}

// ---------------------------------------------------------------------------
// Prep: X fp16 hi/lo split [0,3072); W transpose + single-fp16 [3072,15360);
// blocks [15360,16128): tail copy of rows [0, 1887232) (45% — R12 split).
// ---------------------------------------------------------------------------
__global__ __launch_bounds__(256)
void prep_kernel(const float* __restrict__ Q, const float* __restrict__ K,
                 const float* __restrict__ V,
                 const float* __restrict__ w0, const float* __restrict__ w1,
                 const float* __restrict__ w2,
                 const float* __restrict__ Kcache, const float* __restrict__ Vcache,
                 const int* __restrict__ Cp,
                 float* __restrict__ outKc, float* __restrict__ outVc)
{
    __shared__ float ts[64][65];
    const int bx = blockIdx.x, tid = threadIdx.x;

    if (bx >= 15360) {
        tail_copy(0ull, 1887232ull, 768, bx - 15360, tid, Cp[0],
                  Kcache, Vcache, outKc, outVc);
        return;
    }

    if (bx < 3072) {
        const int proj = bx >> 10;
        const float* src = (proj == 0) ? Q : ((proj == 1) ? K : V);
        const size_t off = ((size_t)(bx & 1023) * 256 + tid) * 8;
        float4 a = *(const float4*)(src + off);
        float4 b = *(const float4*)(src + off + 4);
        float v[8] = {a.x, a.y, a.z, a.w, b.x, b.y, b.z, b.w};
        __align__(16) __half hi[8], lo[8];
#pragma unroll
        for (int j = 0; j < 8; j++) {
            hi[j] = __float2half(v[j]);
            lo[j] = __float2half(v[j] - __half2float(hi[j]));
        }
        const size_t dst = (size_t)proj * (512ull * 4096) + off;
        *(uint4*)(g_Xhi + dst) = *(const uint4*)hi;
        *(uint4*)(g_Xlo + dst) = *(const uint4*)lo;
        return;
    }

    const int wb = bx - 3072;
    const int proj = wb >> 12;
    const int t = wb & 4095;
    const int k0 = (t >> 6) * 64, n0 = (t & 63) * 64;
    const float* W = (proj == 0) ? w0 : ((proj == 1) ? w1 : w2);

    {
        const int r = tid >> 2, c16 = (tid & 3) * 16;
#pragma unroll
        for (int j = 0; j < 4; j++) {
            float4 f = *(const float4*)&W[(size_t)(k0 + r) * 4096 + n0 + c16 + j * 4];
            ts[r][c16 + j * 4 + 0] = f.x;  ts[r][c16 + j * 4 + 1] = f.y;
            ts[r][c16 + j * 4 + 2] = f.z;  ts[r][c16 + j * 4 + 3] = f.w;
        }
    }
    __syncthreads();
    {
        const int nr = tid >> 2, kc = (tid & 3) * 16;
        __align__(16) __half hv[16];
#pragma unroll
        for (int j = 0; j < 16; j++)
            hv[j] = __float2half(ts[kc + j][nr]);
        const size_t base = (size_t)proj * (4096ull * 4096) + (size_t)(n0 + nr) * 4096 + k0 + kc;
        ((uint4*)(g_W + base))[0] = ((const uint4*)hv)[0];
        ((uint4*)(g_W + base))[1] = ((const uint4*)hv)[1];
    }
}

// ---------------------------------------------------------------------------
// tcgen05 GEMM, fp16 3-tensor (Ah,Al,B), cp.async double-buffer (R12 graph).
// Stage = 48KB (Ah,Al,B @ +0/+16384/+32768); 2 blocks/SM. 8 MMAs per chunk.
// ---------------------------------------------------------------------------
__global__ __launch_bounds__(256)
void gemm_kernel(const float* __restrict__ Qin, const float* __restrict__ Kin,
                 const float* __restrict__ Vin,
                 const float* __restrict__ w0, const float* __restrict__ w1,
                 const float* __restrict__ w2,
                 const float* __restrict__ emb, const int* __restrict__ Cp,
                 float* __restrict__ outKc, float* __restrict__ outVc)
{
    const int tid = threadIdx.x;
    const int h = blockIdx.x, m0 = blockIdx.y * 128, which = blockIdx.z;
    const int Cv = Cp[0];

#if HAVE_TCGEN05
    char* sm = _smraw;
    const uint32_t smb = smem_to_u32(sm);
    const int wid = tid >> 5, lane = tid & 31;
    const int n0 = h * 128;

    if (wid == 0) TCGEN05_ALLOC(smb + 0, 512);
    if (tid == 0) { MBARRIER_INIT(smb + 8, 1); MBARRIER_INIT(smb + 16, 1); }
    __syncthreads();
    uint32_t tmem;
    asm volatile("ld.shared.b32 %0, [%1];" : "=r"(tmem) : "r"(smb + 0));

    const int r = tid >> 1;
    const int u0 = (tid & 1) * 4;
    const uint4* pAh = (const uint4*)(g_Xhi + (size_t)which * (512ull * 4096) + (size_t)(m0 + r) * 4096);
    const uint4* pAl = (const uint4*)(g_Xlo + (size_t)which * (512ull * 4096) + (size_t)(m0 + r) * 4096);
    const uint4* pB  = (const uint4*)(g_W   + (size_t)which * (4096ull * 4096) + (size_t)(n0 + r) * 4096);

    uint32_t soff[4];
#pragma unroll
    for (int j = 0; j < 4; j++)
        soff[j] = SMEM_SWIZZLE_128B(r * 128 + (u0 + j) * 16);

#define ISSUE_CP(c, stBase) do { \
        const int kb_ = (c) * 8 + u0; \
        _Pragma("unroll") \
        for (int j = 0; j < 4; j++) CP_ASYNC16((stBase) +         soff[j], pAh + kb_ + j); \
        _Pragma("unroll") \
        for (int j = 0; j < 4; j++) CP_ASYNC16((stBase) + 16384 + soff[j], pAl + kb_ + j); \
        _Pragma("unroll") \
        for (int j = 0; j < 4; j++) CP_ASYNC16((stBase) + 32768 + soff[j], pB  + kb_ + j); \
        CP_COMMIT(); \
    } while (0)

    ISSUE_CP(0, smb + 1024u);
    int ph0 = 0, ph1 = 0;
    for (int c = 0; c < 64; c++) {
        const int st = c & 1;
        const uint32_t so = smb + 1024u + (uint32_t)st * 49152u;
        if (c < 63) {
            const int nst = (c + 1) & 1;
            if (c >= 1) {
                if (nst == 0) { MBARRIER_WAIT_PARITY(smb + 8, ph0); ph0 ^= 1; }
                else          { MBARRIER_WAIT_PARITY(smb + 16, ph1); ph1 ^= 1; }
            }
            ISSUE_CP(c + 1, smb + 1024u + (uint32_t)nst * 49152u);
            CP_WAIT1();
        } else {
            CP_WAIT0();
        }
        __syncthreads();
        FENCE_PROXY_ASYNC();
        if (tid < 32 && elect_one_pred()) {
            const uint64_t dAh = MAKE_SMEM_DESC(so);
            const uint64_t dAl = MAKE_SMEM_DESC(so + 16384);
            const uint64_t dB  = MAKE_SMEM_DESC(so + 32768);
#pragma unroll
            for (int j = 0; j < 4; j++)
                mma_f16_ss(tmem, dAh + j * 2, dB + j * 2, MMA_IDESC_F16, !(c == 0 && j == 0));
#pragma unroll
            for (int j = 0; j < 4; j++)
                mma_f16_ss(tmem, dAl + j * 2, dB + j * 2, MMA_IDESC_F16, true);
            TCGEN05_COMMIT(smb + 8 + st * 8);
        }
    }
    MBARRIER_WAIT_PARITY(smb + 16, ph1);
    TCGEN05_FENCE_AFTER();

    if (wid < 4) {
        const int m = m0 + wid * 32 + lane;
        const int b = m >> 4, s = m & 15;
        const float* cosp = emb + s * HDsz;
        const float* sinp = emb + Ssz * HDsz + s * HDsz;
        float* dst = (which == 0)
            ? g_q + ((size_t)(b * Hsz + h) * Ssz + s) * HDsz
            : ((which == 1)
               ? outKc + ((size_t)(b * Hsz + h) * MAXLEN + (size_t)(Cv + s)) * HDsz
               : outVc + ((size_t)(b * Hsz + h) * MAXLEN + (size_t)(Cv + s)) * HDsz);
#pragma unroll
        for (int p = 0; p < 2; p++) {
            uint32_t x1[32], x2[32];
            TCGEN05_LD_32X32B_X32(x1, tmem + p * 32);
            TCGEN05_LD_32X32B_X32(x2, tmem + 64 + p * 32);
            TCGEN05_WAIT_LD();
            if (which == 2) {
#pragma unroll
                for (int j = 0; j < 32; j++) {
                    dst[p * 32 + j]      = __uint_as_float(x1[j]);
                    dst[64 + p * 32 + j] = __uint_as_float(x2[j]);
                }
            } else {
#pragma unroll
                for (int j = 0; j < 32; j++) {
                    const int d = p * 32 + j;
                    const float a = __uint_as_float(x1[j]);
                    const float bb = __uint_as_float(x2[j]);
                    dst[d]      = a * cosp[d] - bb * sinp[d];
                    dst[d + 64] = bb * cosp[d + 64] + a * sinp[d + 64];
                }
            }
        }
    }
    __syncthreads();
    if (tid == 0) { MBARRIER_INVAL(smb + 8); MBARRIER_INVAL(smb + 16); }
    __syncthreads();
    if (wid == 0) TCGEN05_DEALLOC(tmem, 512);

#else   // ---------------- generic-target fallback: FFMA2 GEMM ----------------
    const float* X = (which == 0) ? Qin : ((which == 1) ? Kin : Vin);
    const float* W = (which == 0) ? w0 : ((which == 1) ? w1 : w2);

    __shared__ float As[2][16][132];
    __shared__ float Bs[2][16][128];

    const int tx = tid & 15;
    const int ty = tid >> 4;
    const int n0f = h * 128;

    float2 acc2[8][4];
#pragma unroll
    for (int i = 0; i < 8; i++)
#pragma unroll
        for (int j = 0; j < 4; j++) acc2[i][j] = make_float2(0.f, 0.f);

    const int r_x = tid >> 2, c_x = tid & 3;
    const int r_w = tid >> 5, c_w = tid & 31;
    float4 xa0, xa1, wb0, wb1;

    xa0 = *(const float4*)&X[(size_t)(m0 + r_x) * Dsz + c_x * 4];
    xa1 = *(const float4*)&X[(size_t)(m0 + r_x + 64) * Dsz + c_x * 4];
    wb0 = *(const float4*)&W[(size_t)(r_w) * Dsz + n0f + c_w * 4];
    wb1 = *(const float4*)&W[(size_t)(r_w + 8) * Dsz + n0f + c_w * 4];

    As[0][c_x * 4 + 0][r_x] = xa0.x;  As[0][c_x * 4 + 1][r_x] = xa0.y;
    As[0][c_x * 4 + 2][r_x] = xa0.z;  As[0][c_x * 4 + 3][r_x] = xa0.w;
    As[0][c_x * 4 + 0][r_x + 64] = xa1.x;  As[0][c_x * 4 + 1][r_x + 64] = xa1.y;
    As[0][c_x * 4 + 2][r_x + 64] = xa1.z;  As[0][c_x * 4 + 3][r_x + 64] = xa1.w;
    *(float4*)&Bs[0][r_w][c_w * 4]     = wb0;
    *(float4*)&Bs[0][r_w + 8][c_w * 4] = wb1;
    __syncthreads();

    int cur = 0;
    for (int kt = 0; kt < 256; kt++) {
        if (kt < 255) {
            const int k0n = (kt + 1) * 16;
            xa0 = *(const float4*)&X[(size_t)(m0 + r_x) * Dsz + k0n + c_x * 4];
            xa1 = *(const float4*)&X[(size_t)(m0 + r_x + 64) * Dsz + k0n + c_x * 4];
            wb0 = *(const float4*)&W[(size_t)(k0n + r_w) * Dsz + n0f + c_w * 4];
            wb1 = *(const float4*)&W[(size_t)(k0n + r_w + 8) * Dsz + n0f + c_w * 4];
        }
#pragma unroll
        for (int k = 0; k < 16; k++) {
            float4 a0 = *(const float4*)&As[cur][k][ty * 8];
            float4 a1 = *(const float4*)&As[cur][k][ty * 8 + 4];
            float4 b0 = *(const float4*)&Bs[cur][k][tx * 4];
            float4 b1 = *(const float4*)&Bs[cur][k][64 + tx * 4];
            const float av[8] = {a0.x, a0.y, a0.z, a0.w, a1.x, a1.y, a1.z, a1.w};
            const float2 bp[4] = {make_float2(b0.x, b0.y), make_float2(b0.z, b0.w),
                                  make_float2(b1.x, b1.y), make_float2(b1.z, b1.w)};
#pragma unroll
            for (int i = 0; i < 8; i++) {
                const float2 ad = make_float2(av[i], av[i]);
#pragma unroll
                for (int jp = 0; jp < 4; jp++)
                    acc2[i][jp] = ffma2(ad, bp[jp], acc2[i][jp]);
            }
        }
        if (kt < 255) {
            const int nb = cur ^ 1;
            As[nb][c_x * 4 + 0][r_x] = xa0.x;  As[nb][c_x * 4 + 1][r_x] = xa0.y;
            As[nb][c_x * 4 + 2][r_x] = xa0.z;  As[nb][c_x * 4 + 3][r_x] = xa0.w;
            As[nb][c_x * 4 + 0][r_x + 64] = xa1.x;  As[nb][c_x * 4 + 1][r_x + 64] = xa1.y;
            As[nb][c_x * 4 + 2][r_x + 64] = xa1.z;  As[nb][c_x * 4 + 3][r_x + 64] = xa1.w;
            *(float4*)&Bs[nb][r_w][c_w * 4]     = wb0;
            *(float4*)&Bs[nb][r_w + 8][c_w * 4] = wb1;
        }
        __syncthreads();
        cur ^= 1;
    }

#pragma unroll
    for (int i = 0; i < 8; i++) {
        const int m = m0 + ty * 8 + i;
        const int b = m >> 4;
        const int s = m & 15;
        const float* accr = (const float*)&acc2[i][0];
        if (which == 2) {
            float* vb = outVc + ((size_t)(b * Hsz + h) * MAXLEN + (size_t)(Cv + s)) * HDsz;
#pragma unroll
            for (int j = 0; j < 4; j++) {
                vb[tx * 4 + j]      = accr[j];
                vb[64 + tx * 4 + j] = accr[j + 4];
            }
        } else {
            const float* cosp = emb + s * HDsz;
            const float* sinp = emb + Ssz * HDsz + s * HDsz;
            float* dst = (which == 0)
                ? (g_q + ((size_t)(b * Hsz + h) * Ssz + s) * HDsz)
                : (outKc + ((size_t)(b * Hsz + h) * MAXLEN + (size_t)(Cv + s)) * HDsz);
#pragma unroll
            for (int j = 0; j < 4; j++) {
                const int d1 = tx * 4 + j;
                const float x1 = accr[j];
                const float x2 = accr[j + 4];
                dst[d1]      = x1 * cosp[d1]      - x2 * sinp[d1];
                dst[d1 + 64] = x2 * cosp[d1 + 64] + x1 * sinp[d1 + 64];
            }
        }
    }
#endif
}

// ---------------------------------------------------------------------------
// Attention (R12-proven): blocks [0,1024) one (b,h) each with write-through of
// rows < C; blocks [1024,1536) copy tail rows [1887232, 4194304).
// ---------------------------------------------------------------------------
__global__ __launch_bounds__(256)
void attn_kernel(const float* __restrict__ KcOld, const float* __restrict__ VcOld,
                 const int* __restrict__ Cp, float* __restrict__ out,
                 float* __restrict__ outKc, float* __restrict__ outVc)
{
    const int tid = threadIdx.x;
    const int Cv = Cp[0];

    if (blockIdx.x >= 1024) {
        tail_copy(1887232ull, 4194304ull, 512, blockIdx.x - 1024, tid, Cv,
                  KcOld, VcOld, outKc, outVc);
        return;
    }

    float* sm = (float*)_smraw;
    float* qs = sm;
    float* Ks = sm + 2048;
    float* Vs = Ks + 64 * 132;

    const int w = tid >> 5;
    const int l = tid & 31;
    const int bh = blockIdx.x;
    const int Lv = Cv + Ssz;

    const float* KbO = KcOld + (size_t)bh * MAXLEN * HDsz;
    const float* VbO = VcOld + (size_t)bh * MAXLEN * HDsz;
    float* KbN = outKc + (size_t)bh * MAXLEN * HDsz;
    float* VbN = outVc + (size_t)bh * MAXLEN * HDsz;
    const float* qg = g_q + (size_t)bh * Ssz * HDsz;

    for (int f = tid; f < Ssz * HDsz / 4; f += 256)
        ((float4*)qs)[f] = ((const float4*)qg)[f];

    const int q0 = 2 * w, q1 = 2 * w + 1;
    float m0r = -1e30f, m1r = -1e30f, l0r = 0.f, l1r = 0.f;
    float2 o0[2] = {make_float2(0.f, 0.f), make_float2(0.f, 0.f)};
    float2 o1[2] = {make_float2(0.f, 0.f), make_float2(0.f, 0.f)};
    const float SCALE = 0.08838834764831845f;
    const int ntiles = (Lv + 63) >> 6;

    for (int t = 0; t < ntiles; t++) {
        const int tile0 = t << 6;
        __syncthreads();
        for (int f = tid; f < 64 * 32; f += 256) {
            const int key = f >> 5;
            const int d4 = (f & 31) * 4;
            const int pos = tile0 + key;
            const size_t gi = (size_t)pos * HDsz + d4;
            float4 kv, vv;
            if (pos < Cv) {
                kv = *(const float4*)&KbO[gi];
                vv = *(const float4*)&VbO[gi];
                *(float4*)&KbN[gi] = kv;
                *(float4*)&VbN[gi] = vv;
            } else {
                kv = *(const float4*)&KbN[gi];
                vv = *(const float4*)&VbN[gi];
            }
            *(float4*)&Ks[key * 132 + d4] = kv;
            *(float4*)&Vs[key * 132 + d4] = vv;
        }
        __syncthreads();

        const float4* kr0 = (const float4*)(Ks + l * 132);
        const float4* kr1 = (const float4*)(Ks + (l + 32) * 132);
        const float4* qr0 = (const float4*)(qs + q0 * HDsz);
        const float4* qr1 = (const float4*)(qs + q1 * HDsz);
        float2 s00 = make_float2(0.f, 0.f), s01 = s00, s10 = s00, s11 = s00;
#pragma unroll 8
        for (int d4 = 0; d4 < 32; d4++) {
            const float4 qa = qr0[d4], qb = qr1[d4];
            const float4 ka = kr0[d4], kb = kr1[d4];
            const float2 qa0 = make_float2(qa.x, qa.y), qa1 = make_float2(qa.z, qa.w);
            const float2 qb0 = make_float2(qb.x, qb.y), qb1 = make_float2(qb.z, qb.w);
            const float2 ka0 = make_float2(ka.x, ka.y), ka1 = make_float2(ka.z, ka.w);
            const float2 kb0 = make_float2(kb.x, kb.y), kb1 = make_float2(kb.z, kb.w);
            s00 = ffma2(qa0, ka0, s00);  s00 = ffma2(qa1, ka1, s00);
            s01 = ffma2(qa0, kb0, s01);  s01 = ffma2(qa1, kb1, s01);
            s10 = ffma2(qb0, ka0, s10);  s10 = ffma2(qb1, ka1, s10);
            s11 = ffma2(qb0, kb0, s11);  s11 = ffma2(qb1, kb1, s11);
        }
        const int kp0 = tile0 + l, kp1 = tile0 + l + 32;
        const int qp0 = Cv + q0,  qp1 = Cv + q1;
        float x00 = (kp0 < Lv && kp0 <= qp0) ? (s00.x + s00.y) * SCALE : -1e30f;
        float x01 = (kp1 < Lv && kp1 <= qp0) ? (s01.x + s01.y) * SCALE : -1e30f;
        float x10 = (kp0 < Lv && kp0 <= qp1) ? (s10.x + s10.y) * SCALE : -1e30f;
        float x11 = (kp1 < Lv && kp1 <= qp1) ? (s11.x + s11.y) * SCALE : -1e30f;

        float mt0 = fmaxf(x00, x01);
        float mt1 = fmaxf(x10, x11);
#pragma unroll
        for (int off = 16; off; off >>= 1) {
            mt0 = fmaxf(mt0, __shfl_xor_sync(0xffffffffu, mt0, off));
            mt1 = fmaxf(mt1, __shfl_xor_sync(0xffffffffu, mt1, off));
        }
        const float nm0 = fmaxf(m0r, mt0), nm1 = fmaxf(m1r, mt1);
        const float f0 = __expf(m0r - nm0), f1 = __expf(m1r - nm1);
        const float p00 = __expf(x00 - nm0), p01 = __expf(x01 - nm0);
        const float p10 = __expf(x10 - nm1), p11 = __expf(x11 - nm1);
        float sum0 = p00 + p01, sum1 = p10 + p11;
#pragma unroll
        for (int off = 16; off; off >>= 1) {
            sum0 += __shfl_xor_sync(0xffffffffu, sum0, off);
            sum1 += __shfl_xor_sync(0xffffffffu, sum1, off);
        }
        l0r = l0r * f0 + sum0;  l1r = l1r * f1 + sum1;
        m0r = nm0;  m1r = nm1;
        o0[0].x *= f0; o0[0].y *= f0; o0[1].x *= f0; o0[1].y *= f0;
        o1[0].x *= f1; o1[0].y *= f1; o1[1].x *= f1; o1[1].y *= f1;

#pragma unroll 8
        for (int k = 0; k < 32; k++) {
            const float pv0 = __shfl_sync(0xffffffffu, p00, k);
            const float pv1 = __shfl_sync(0xffffffffu, p10, k);
            const float4 v4 = *(const float4*)&Vs[k * 132 + l * 4];
            const float2 vp0 = make_float2(v4.x, v4.y), vp1 = make_float2(v4.z, v4.w);
            const float2 pv02 = make_float2(pv0, pv0), pv12 = make_float2(pv1, pv1);
            o0[0] = ffma2(pv02, vp0, o0[0]);  o0[1] = ffma2(pv02, vp1, o0[1]);
            o1[0] = ffma2(pv12, vp0, o1[0]);  o1[1] = ffma2(pv12, vp1, o1[1]);
        }
#pragma unroll 8
        for (int k = 0; k < 32; k++) {
            const float pv0 = __shfl_sync(0xffffffffu, p01, k);
            const float pv1 = __shfl_sync(0xffffffffu, p11, k);
            const float4 v4 = *(const float4*)&Vs[(k + 32) * 132 + l * 4];
            const float2 vp0 = make_float2(v4.x, v4.y), vp1 = make_float2(v4.z, v4.w);
            const float2 pv02 = make_float2(pv0, pv0), pv12 = make_float2(pv1, pv1);
            o0[0] = ffma2(pv02, vp0, o0[0]);  o0[1] = ffma2(pv02, vp1, o0[1]);
            o1[0] = ffma2(pv12, vp0, o1[0]);  o1[1] = ffma2(pv12, vp1, o1[1]);
        }
    }

    const int b = bh >> 5;
    const int h = bh & 31;
    const float inv0 = 1.f / l0r, inv1 = 1.f / l1r;
    float4 r0 = make_float4(o0[0].x * inv0, o0[0].y * inv0, o0[1].x * inv0, o0[1].y * inv0);
    float4 r1 = make_float4(o1[0].x * inv1, o1[0].y * inv1, o1[1].x * inv1, o1[1].y * inv1);
    *(float4*)&out[((size_t)(b * Ssz + q0) * Dsz) + h * HDsz + l * 4] = r0;
    *(float4*)&out[((size_t)(b * Ssz + q1) * Dsz) + h * HDsz + l * 4] = r1;
}

// ---------------------------------------------------------------------------
extern "C" void kernel_launch(void* const* d_in, const int* in_sizes, int n_in,
                              void* d_out, int out_size)
{
    const float* Q      = (const float*)d_in[0];
    const float* K      = (const float*)d_in[1];
    const float* V      = (const float*)d_in[2];
    const float* Kcache = (const float*)d_in[3];
    const float* Vcache = (const float*)d_in[4];
    const float* w0     = (const float*)d_in[5];
    const float* w1     = (const float*)d_in[6];
    const float* w2     = (const float*)d_in[7];
    const float* emb    = (const float*)d_in[8];
    const int*   Cp     = (const int*)d_in[9];
    float* out = (float*)d_out;

    const size_t outsz   = (size_t)Bsz * Ssz * Dsz;
    const size_t cachesz = (size_t)Bsz * Hsz * MAXLEN * HDsz;
    float* outKc = out + outsz;
    float* outVc = outKc + cachesz;

    // 1) prep (X fp16 split + W fp16 transpose) + 45% of tail copy
    prep_kernel<<<16128, 256>>>(Q, K, V, w0, w1, w2, Kcache, Vcache, Cp, outKc, outVc);

    // 2) projections: tcgen05 fp16 3-tensor + cp.async pipeline (2 blocks/SM)
    const int gsmem = 1024 + 2 * 49152;   // 99,328 B
    cudaFuncSetAttribute(gemm_kernel, cudaFuncAttributeMaxDynamicSharedMemorySize, gsmem);
    gemm_kernel<<<dim3(32, 4, 3), 256, gsmem>>>(Q, K, V, w0, w1, w2, emb, Cp, outKc, outVc);

    // 3) attention + write-through + remaining tail copy
    const int asmem = (16 * 128 + 2 * 64 * 132) * 4;   // 75,776 B
    cudaFuncSetAttribute(attn_kernel, cudaFuncAttributeMaxDynamicSharedMemorySize, asmem);
    attn_kernel<<<1536, 256, asmem>>>(Kcache, Vcache, Cp, out, outKc, outVc);
}